// round 1
// baseline (speedup 1.0000x reference)
#include <cuda_runtime.h>
#include <math.h>

#define BATCH 2
#define SEQ   2048
#define DIM   1024
#define ROWS  (BATCH*SEQ)   // 4096
#define NH    16
#define DH    64

// Scratch (allocation-free rule: __device__ globals)
__device__ float g_xn[ROWS*DIM];
__device__ float g_q [ROWS*DIM];
__device__ float g_k [ROWS*DIM];
__device__ float g_v [ROWS*DIM];
__device__ float g_ao[ROWS*DIM];

// ---------------------------------------------------------------------------
// RMSNorm: one block per row
// ---------------------------------------------------------------------------
__global__ __launch_bounds__(256) void rmsnorm_kernel(
    const float* __restrict__ x, const float* __restrict__ sc,
    float* __restrict__ y)
{
    int row = blockIdx.x;
    const float* xr = x + (size_t)row * DIM;
    float ss = 0.f;
    #pragma unroll
    for (int i = threadIdx.x; i < DIM; i += 256) {
        float v = xr[i];
        ss = fmaf(v, v, ss);
    }
    __shared__ float red[256];
    red[threadIdx.x] = ss;
    __syncthreads();
    #pragma unroll
    for (int s = 128; s > 0; s >>= 1) {
        if (threadIdx.x < s) red[threadIdx.x] += red[threadIdx.x + s];
        __syncthreads();
    }
    float r = rsqrtf(red[0] * (1.0f / DIM) + 1e-6f);
    float* yr = y + (size_t)row * DIM;
    #pragma unroll
    for (int i = threadIdx.x; i < DIM; i += 256)
        yr[i] = xr[i] * r * sc[i];
}

// ---------------------------------------------------------------------------
// Tiled fp32 GEMM: C[M,N] = A[M,K] @ B[K,N]
// BM=128, BN=64, BK=16; 256 threads; 8x4 per-thread microtile
// ---------------------------------------------------------------------------
#define GBM 128
#define GBN 64
#define GBK 16

__global__ __launch_bounds__(256) void gemm_kernel(
    const float* __restrict__ A, const float* __restrict__ B,
    float* __restrict__ C, int M, int N, int K)
{
    __shared__ float As[GBK][GBM];
    __shared__ float Bs[GBK][GBN];

    int tid = threadIdx.x;
    int tx = tid & 15;       // 0..15 -> N
    int ty = tid >> 4;       // 0..15 -> M
    int bm = blockIdx.y * GBM;
    int bn = blockIdx.x * GBN;

    float acc[8][4];
    #pragma unroll
    for (int i = 0; i < 8; i++)
        #pragma unroll
        for (int j = 0; j < 4; j++)
            acc[i][j] = 0.f;

    for (int k0 = 0; k0 < K; k0 += GBK) {
        // Load A tile: 128x16 = 512 float4, 2 per thread, store transposed
        #pragma unroll
        for (int f = tid; f < 512; f += 256) {
            int r  = f >> 2;
            int c4 = (f & 3) << 2;
            float4 va = *(const float4*)&A[(size_t)(bm + r) * K + k0 + c4];
            As[c4 + 0][r] = va.x;
            As[c4 + 1][r] = va.y;
            As[c4 + 2][r] = va.z;
            As[c4 + 3][r] = va.w;
        }
        // Load B tile: 16x64 = 256 float4, 1 per thread
        {
            int r  = tid >> 4;
            int c4 = (tid & 15) << 2;
            *(float4*)&Bs[r][c4] =
                *(const float4*)&B[(size_t)(k0 + r) * N + bn + c4];
        }
        __syncthreads();

        #pragma unroll
        for (int kk = 0; kk < GBK; kk++) {
            float a[8], bb[4];
            *(float4*)&a[0] = *(float4*)&As[kk][ty * 8];
            *(float4*)&a[4] = *(float4*)&As[kk][ty * 8 + 4];
            *(float4*)&bb[0] = *(float4*)&Bs[kk][tx * 4];
            #pragma unroll
            for (int i = 0; i < 8; i++)
                #pragma unroll
                for (int j = 0; j < 4; j++)
                    acc[i][j] = fmaf(a[i], bb[j], acc[i][j]);
        }
        __syncthreads();
    }

    #pragma unroll
    for (int i = 0; i < 8; i++) {
        float4 vo = make_float4(acc[i][0], acc[i][1], acc[i][2], acc[i][3]);
        *(float4*)&C[(size_t)(bm + ty * 8 + i) * N + bn + tx * 4] = vo;
    }
}

// ---------------------------------------------------------------------------
// RoPE in-place on q and k. One thread per (tensor, row, head, pair-index).
// Mirrors the jax fp32 math: theta = 1/base^(2i/dim), angle = pos*theta.
// ---------------------------------------------------------------------------
__global__ __launch_bounds__(256) void rope_kernel(
    float* __restrict__ q, float* __restrict__ k)
{
    int idx = blockIdx.x * blockDim.x + threadIdx.x;
    // total = 2 * ROWS * NH * (DH/2) = 2 * 4096 * 16 * 32 = 2^22
    int half = idx >> 21;            // 0=q, 1=k
    int r    = idx & ((1 << 21) - 1);
    int row  = r >> 9;               // 512 = NH * 32
    int rem  = r & 511;
    int head = rem >> 5;
    int i    = rem & 31;

    float* p = (half ? k : q) + (size_t)row * DIM + head * DH;
    int pos = row & (SEQ - 1);

    float e = (2.0f * (float)i) / (float)DH;
    float theta = 1.0f / powf(1.0e6f, e);
    float angle = (float)pos * theta;
    float sn, cs;
    __sincosf(angle, &sn, &cs);
    // use accurate versions to match jnp closely
    sn = sinf(angle);
    cs = cosf(angle);

    float x1 = p[i];
    float x2 = p[i + 32];
    p[i]      = x1 * cs - x2 * sn;
    p[i + 32] = x1 * sn + x2 * cs;
}

// ---------------------------------------------------------------------------
// Flash-style causal attention (fp32, no online max: scores ~N(0,1), no
// overflow possible; softmax computed as sum-of-exp then normalize).
// Block: 128 threads = 128 query rows; K/V tiles of 32 keys in smem.
// grid.x = SEQ/128 (q tiles, reversed so heavy blocks launch first),
// grid.y = BATCH*NH.
// ---------------------------------------------------------------------------
__global__ __launch_bounds__(128) void flash_kernel(
    const float* __restrict__ q, const float* __restrict__ k,
    const float* __restrict__ v, float* __restrict__ o)
{
    __shared__ float Ks[32][64];
    __shared__ float Vs[32][64];

    int bh = blockIdx.y;
    int b  = bh >> 4;
    int h  = bh & 15;
    int qt = (gridDim.x - 1) - blockIdx.x;   // heavy tiles first
    int q0 = qt * 128;
    int tid = threadIdx.x;
    int qi = q0 + tid;                       // query index within sequence

    const float* qrow = q + (size_t)(b * SEQ + qi) * DIM + h * DH;
    float qv[64];
    #pragma unroll
    for (int d = 0; d < 64; d += 4)
        *(float4*)&qv[d] = *(const float4*)&qrow[d];

    float acc[64];
    #pragma unroll
    for (int d = 0; d < 64; d++) acc[d] = 0.f;
    float l = 0.f;

    const float* kb = k + (size_t)b * SEQ * DIM + h * DH;
    const float* vb = v + (size_t)b * SEQ * DIM + h * DH;

    int ntiles = (q0 >> 5) + 4;   // keys up to q0+127 inclusive

    for (int t = 0; t < ntiles; t++) {
        int k0 = t << 5;
        __syncthreads();
        // load 32x64 K and V tiles (512 float4 each half), coalesced
        #pragma unroll
        for (int f = tid; f < 512; f += 128) {
            int r = f >> 4;
            int c = (f & 15) << 2;
            *(float4*)&Ks[r][c] = *(const float4*)&kb[(size_t)(k0 + r) * DIM + c];
            *(float4*)&Vs[r][c] = *(const float4*)&vb[(size_t)(k0 + r) * DIM + c];
        }
        __syncthreads();

        for (int j = 0; j < 32; j++) {
            float s0 = 0.f, s1 = 0.f, s2 = 0.f, s3 = 0.f;
            #pragma unroll
            for (int d4 = 0; d4 < 16; d4++) {
                float4 kk = *(const float4*)&Ks[j][d4 * 4];
                s0 = fmaf(qv[d4 * 4 + 0], kk.x, s0);
                s1 = fmaf(qv[d4 * 4 + 1], kk.y, s1);
                s2 = fmaf(qv[d4 * 4 + 2], kk.z, s2);
                s3 = fmaf(qv[d4 * 4 + 3], kk.w, s3);
            }
            float sj = ((s0 + s1) + (s2 + s3)) * 0.125f;  // 1/sqrt(64)
            float p = (k0 + j <= qi) ? expf(sj) : 0.f;
            l += p;
            #pragma unroll
            for (int d4 = 0; d4 < 16; d4++) {
                float4 vv = *(const float4*)&Vs[j][d4 * 4];
                acc[d4 * 4 + 0] = fmaf(p, vv.x, acc[d4 * 4 + 0]);
                acc[d4 * 4 + 1] = fmaf(p, vv.y, acc[d4 * 4 + 1]);
                acc[d4 * 4 + 2] = fmaf(p, vv.z, acc[d4 * 4 + 2]);
                acc[d4 * 4 + 3] = fmaf(p, vv.w, acc[d4 * 4 + 3]);
            }
        }
    }

    float inv = 1.0f / l;
    float* orow = o + (size_t)(b * SEQ + qi) * DIM + h * DH;
    #pragma unroll
    for (int d = 0; d < 64; d += 4) {
        float4 vo = make_float4(acc[d] * inv, acc[d + 1] * inv,
                                acc[d + 2] * inv, acc[d + 3] * inv);
        *(float4*)&orow[d] = vo;
    }
}

// ---------------------------------------------------------------------------
// Launch
// ---------------------------------------------------------------------------
extern "C" void kernel_launch(void* const* d_in, const int* in_sizes, int n_in,
                              void* d_out, int out_size)
{
    (void)in_sizes; (void)n_in; (void)out_size;
    const float* x  = (const float*)d_in[0];
    const float* ns = (const float*)d_in[1];
    const float* Wq = (const float*)d_in[2];
    const float* Wk = (const float*)d_in[3];
    const float* Wv = (const float*)d_in[4];
    const float* Wo = (const float*)d_in[5];
    float* out = (float*)d_out;

    float *xn, *qb, *kb, *vb, *ao;
    cudaGetSymbolAddress((void**)&xn, g_xn);
    cudaGetSymbolAddress((void**)&qb, g_q);
    cudaGetSymbolAddress((void**)&kb, g_k);
    cudaGetSymbolAddress((void**)&vb, g_v);
    cudaGetSymbolAddress((void**)&ao, g_ao);

    rmsnorm_kernel<<<ROWS, 256>>>(x, ns, xn);

    dim3 gg(DIM / GBN, ROWS / GBM);   // (16, 32)
    gemm_kernel<<<gg, 256>>>(xn, Wq, qb, ROWS, DIM, DIM);
    gemm_kernel<<<gg, 256>>>(xn, Wk, kb, ROWS, DIM, DIM);
    gemm_kernel<<<gg, 256>>>(xn, Wv, vb, ROWS, DIM, DIM);

    // 2 tensors * 4096 rows * 16 heads * 32 pairs = 2^22 threads
    rope_kernel<<<(2 * ROWS * NH * (DH / 2)) / 256, 256>>>(qb, kb);

    flash_kernel<<<dim3(SEQ / 128, BATCH * NH), 128>>>(qb, kb, vb, ao);

    gemm_kernel<<<gg, 256>>>(ao, Wo, out, ROWS, DIM, DIM);
}

// round 3
// speedup vs baseline: 1.5745x; 1.5745x over previous
#include <cuda_runtime.h>
#include <cuda_bf16.h>
#include <stdint.h>
#include <math.h>

#define BATCH 2
#define SEQ   2048
#define DIM   1024
#define ROWS  (BATCH*SEQ)   // 4096
#define NH    16
#define DH    64

// Scratch (allocation-free rule: __device__ globals)
__device__ float g_xn[ROWS*DIM];
__device__ float g_q [ROWS*DIM];
__device__ float g_k [ROWS*DIM];
__device__ float g_v [ROWS*DIM];
__device__ float g_ao[ROWS*DIM];
__device__ __nv_bfloat16 g_ah[ROWS*DIM];   // A split hi
__device__ __nv_bfloat16 g_al[ROWS*DIM];   // A split lo
__device__ __nv_bfloat16 g_th[DIM*DIM];    // W^T split hi  [N][K]
__device__ __nv_bfloat16 g_tl[DIM*DIM];    // W^T split lo  [N][K]

// ===========================================================================
// Portable (compute_103-safe) PTX helpers: mma.sync / ldmatrix / cp.async
// ===========================================================================
__device__ __forceinline__ uint32_t smem_u32(const void* p) {
    uint32_t a;
    asm("{ .reg .u64 t; cvta.to.shared.u64 t, %1; cvt.u32.u64 %0, t; }"
        : "=r"(a) : "l"(p));
    return a;
}
__device__ __forceinline__ void cp_async16(uint32_t saddr, const void* gaddr) {
    asm volatile("cp.async.cg.shared.global [%0], [%1], 16;"
                 :: "r"(saddr), "l"(gaddr));
}
__device__ __forceinline__ void cp_commit() {
    asm volatile("cp.async.commit_group;" ::: "memory");
}
__device__ __forceinline__ void ldsm4(uint32_t* r, uint32_t addr) {
    asm volatile("ldmatrix.sync.aligned.m8n8.x4.shared.b16 {%0,%1,%2,%3}, [%4];"
                 : "=r"(r[0]), "=r"(r[1]), "=r"(r[2]), "=r"(r[3]) : "r"(addr));
}
__device__ __forceinline__ void mma16816(float* c, const uint32_t* a,
                                         uint32_t b0, uint32_t b1) {
    asm volatile(
        "mma.sync.aligned.m16n8k16.row.col.f32.bf16.bf16.f32 "
        "{%0,%1,%2,%3}, {%4,%5,%6,%7}, {%8,%9}, {%0,%1,%2,%3};"
        : "+f"(c[0]), "+f"(c[1]), "+f"(c[2]), "+f"(c[3])
        : "r"(a[0]), "r"(a[1]), "r"(a[2]), "r"(a[3]), "r"(b0), "r"(b1));
}

// ===========================================================================
// RMSNorm: one block per row
// ===========================================================================
__global__ __launch_bounds__(256) void rmsnorm_kernel(
    const float* __restrict__ x, const float* __restrict__ sc,
    float* __restrict__ y)
{
    int row = blockIdx.x;
    const float* xr = x + (size_t)row * DIM;
    float ss = 0.f;
    #pragma unroll
    for (int i = threadIdx.x; i < DIM; i += 256) {
        float v = xr[i];
        ss = fmaf(v, v, ss);
    }
    __shared__ float red[256];
    red[threadIdx.x] = ss;
    __syncthreads();
    #pragma unroll
    for (int s = 128; s > 0; s >>= 1) {
        if (threadIdx.x < s) red[threadIdx.x] += red[threadIdx.x + s];
        __syncthreads();
    }
    float r = rsqrtf(red[0] * (1.0f / DIM) + 1e-6f);
    float* yr = y + (size_t)row * DIM;
    #pragma unroll
    for (int i = threadIdx.x; i < DIM; i += 256)
        yr[i] = xr[i] * r * sc[i];
}

// ===========================================================================
// Split fp32 -> bf16 (hi, lo). One thread per 4 elements.
// ===========================================================================
__global__ __launch_bounds__(256) void asplit_kernel(
    const float* __restrict__ x,
    __nv_bfloat16* __restrict__ hi, __nv_bfloat16* __restrict__ lo)
{
    int i = (blockIdx.x * 256 + threadIdx.x) * 4;
    float4 v = *(const float4*)(x + i);
    __nv_bfloat16 h0 = __float2bfloat16(v.x);
    __nv_bfloat16 h1 = __float2bfloat16(v.y);
    __nv_bfloat16 h2 = __float2bfloat16(v.z);
    __nv_bfloat16 h3 = __float2bfloat16(v.w);
    *(__nv_bfloat162*)(hi + i)     = __halves2bfloat162(h0, h1);
    *(__nv_bfloat162*)(hi + i + 2) = __halves2bfloat162(h2, h3);
    __nv_bfloat16 l0 = __float2bfloat16(v.x - __bfloat162float(h0));
    __nv_bfloat16 l1 = __float2bfloat16(v.y - __bfloat162float(h1));
    __nv_bfloat16 l2 = __float2bfloat16(v.z - __bfloat162float(h2));
    __nv_bfloat16 l3 = __float2bfloat16(v.w - __bfloat162float(h3));
    *(__nv_bfloat162*)(lo + i)     = __halves2bfloat162(l0, l1);
    *(__nv_bfloat162*)(lo + i + 2) = __halves2bfloat162(l2, l3);
}

// ===========================================================================
// Transpose + split: W [K=1024][N=1024] fp32 -> T_hi/T_lo [N][K] bf16
// ===========================================================================
__global__ __launch_bounds__(256) void wsplit_kernel(
    const float* __restrict__ W,
    __nv_bfloat16* __restrict__ Th, __nv_bfloat16* __restrict__ Tl)
{
    __shared__ float tile[32][33];
    int k0 = blockIdx.y * 32, n0 = blockIdx.x * 32;
    int tx = threadIdx.x & 31, ty = threadIdx.x >> 5;   // 32 x 8
    #pragma unroll
    for (int i = 0; i < 32; i += 8)
        tile[ty + i][tx] = W[(size_t)(k0 + ty + i) * DIM + n0 + tx];
    __syncthreads();
    #pragma unroll
    for (int i = 0; i < 32; i += 8) {
        float v = tile[tx][ty + i];    // = W[k0+tx][n0+ty+i]
        __nv_bfloat16 h = __float2bfloat16(v);
        float r = v - __bfloat162float(h);
        size_t o = (size_t)(n0 + ty + i) * DIM + k0 + tx;
        Th[o] = h;
        Tl[o] = __float2bfloat16(r);
    }
}

// ===========================================================================
// bf16-split GEMM via mma.sync: C[4096,1024] = A @ W
// A as (Ah,Al) [M][K] bf16; W transposed as (Bh,Bl) [N][K] bf16.
// Block tile 128x128, BK=32, 8 warps (4x2), warp tile 32x64.
// 3 mma passes per k-step: AhBh + AhBl + AlBh (AlBl dropped, ~2^-17 rel).
// cp.async double-buffered pipeline, SMEM rows padded to 80B (ldmatrix
// conflict-free: row words 20r mod 32 all distinct).
// ===========================================================================
#define TILE_B  10240              // 128 rows x 80 bytes
#define STAGE_B (4*TILE_B)         // Ah,Al,Bh,Bl
#define GEMM_SMEM (2*STAGE_B)      // 81920

__global__ __launch_bounds__(256) void mma_gemm_kernel(
    const __nv_bfloat16* __restrict__ Ah, const __nv_bfloat16* __restrict__ Al,
    const __nv_bfloat16* __restrict__ Bh, const __nv_bfloat16* __restrict__ Bl,
    float* __restrict__ C)
{
    extern __shared__ char smem[];
    uint32_t sb = smem_u32(smem);

    const int tid  = threadIdx.x;
    const int lane = tid & 31;
    const int wid  = tid >> 5;
    const int warp_m = wid & 3;        // 0..3 -> 32-row slab
    const int warp_n = wid >> 2;       // 0..1 -> 64-col slab
    const int bm = blockIdx.y * 128;
    const int bn = blockIdx.x * 128;

    const __nv_bfloat16* gsrc[4] = {Ah, Al, Bh, Bl};

    float acc[2][8][4];
    #pragma unroll
    for (int i = 0; i < 2; i++)
        #pragma unroll
        for (int j = 0; j < 8; j++)
            #pragma unroll
            for (int q = 0; q < 4; q++) acc[i][j][q] = 0.f;

    // ---- G2S loader for one K-tile into stage s ----
    auto load_stage = [&](int kt, int s) {
        #pragma unroll
        for (int t = 0; t < 4; t++) {
            const __nv_bfloat16* src = gsrc[t];
            int row0 = (t < 2) ? bm : bn;
            #pragma unroll
            for (int i = 0; i < 2; i++) {
                int chunk = tid + i * 256;         // 0..511
                int row = chunk >> 2;
                int c   = chunk & 3;               // 16B unit within row
                const void* g = src + (size_t)(row0 + row) * DIM + kt * 32 + c * 8;
                uint32_t sa = sb + s * STAGE_B + t * TILE_B + row * 80 + c * 16;
                cp_async16(sa, g);
            }
        }
        cp_commit();
    };

    load_stage(0, 0);
    load_stage(1, 1);

    // ldmatrix lane->address coords
    const int aRow = lane & 15;
    const int aK16 = (lane >> 4) * 16;            // byte offset for k8 half
    const int bRow = (lane & 7) + ((lane >> 4) << 3);
    const int bK16 = ((lane >> 3) & 1) * 16;

    for (int kt = 0; kt < 32; kt++) {
        if (kt < 31) asm volatile("cp.async.wait_group 1;" ::: "memory");
        else         asm volatile("cp.async.wait_group 0;" ::: "memory");
        __syncthreads();

        uint32_t st = sb + (kt & 1) * STAGE_B;
        uint32_t aH = st + 0 * TILE_B + (warp_m * 32 + aRow) * 80 + aK16;
        uint32_t aL = st + 1 * TILE_B + (warp_m * 32 + aRow) * 80 + aK16;
        uint32_t bH = st + 2 * TILE_B + (warp_n * 64 + bRow) * 80 + bK16;
        uint32_t bL = st + 3 * TILE_B + (warp_n * 64 + bRow) * 80 + bK16;

        #pragma unroll
        for (int ks = 0; ks < 2; ks++) {
            uint32_t koff = ks * 32;               // 16 bf16 = 32 bytes
            uint32_t fah[2][4], fal[2][4], fbh[4][4], fbl[4][4];
            #pragma unroll
            for (int mt = 0; mt < 2; mt++) {
                ldsm4(fah[mt], aH + mt * 16 * 80 + koff);
                ldsm4(fal[mt], aL + mt * 16 * 80 + koff);
            }
            #pragma unroll
            for (int nt2 = 0; nt2 < 4; nt2++) {
                ldsm4(fbh[nt2], bH + nt2 * 16 * 80 + koff);
                ldsm4(fbl[nt2], bL + nt2 * 16 * 80 + koff);
            }
            // combo 1: Ah * Bh
            #pragma unroll
            for (int mt = 0; mt < 2; mt++)
                #pragma unroll
                for (int nt = 0; nt < 8; nt++)
                    mma16816(acc[mt][nt], fah[mt],
                             fbh[nt >> 1][(nt & 1) * 2], fbh[nt >> 1][(nt & 1) * 2 + 1]);
            // combo 2: Ah * Bl
            #pragma unroll
            for (int mt = 0; mt < 2; mt++)
                #pragma unroll
                for (int nt = 0; nt < 8; nt++)
                    mma16816(acc[mt][nt], fah[mt],
                             fbl[nt >> 1][(nt & 1) * 2], fbl[nt >> 1][(nt & 1) * 2 + 1]);
            // combo 3: Al * Bh
            #pragma unroll
            for (int mt = 0; mt < 2; mt++)
                #pragma unroll
                for (int nt = 0; nt < 8; nt++)
                    mma16816(acc[mt][nt], fal[mt],
                             fbh[nt >> 1][(nt & 1) * 2], fbh[nt >> 1][(nt & 1) * 2 + 1]);
        }
        __syncthreads();
        if (kt + 2 < 32) load_stage(kt + 2, kt & 1);
    }

    // Epilogue: c0,c1 -> (row g, col 2t,2t+1); c2,c3 -> row g+8
    const int g = lane >> 2, t2 = (lane & 3) * 2;
    #pragma unroll
    for (int mt = 0; mt < 2; mt++) {
        #pragma unroll
        for (int nt = 0; nt < 8; nt++) {
            int row = bm + warp_m * 32 + mt * 16 + g;
            int col = bn + warp_n * 64 + nt * 8 + t2;
            *(float2*)&C[(size_t)row * DIM + col] =
                make_float2(acc[mt][nt][0], acc[mt][nt][1]);
            *(float2*)&C[(size_t)(row + 8) * DIM + col] =
                make_float2(acc[mt][nt][2], acc[mt][nt][3]);
        }
    }
}

// ===========================================================================
// RoPE in-place on q and k.
// ===========================================================================
__global__ __launch_bounds__(256) void rope_kernel(
    float* __restrict__ q, float* __restrict__ k)
{
    int idx = blockIdx.x * blockDim.x + threadIdx.x;
    int half = idx >> 21;            // 0=q, 1=k
    int r    = idx & ((1 << 21) - 1);
    int row  = r >> 9;               // 512 = NH * 32
    int rem  = r & 511;
    int head = rem >> 5;
    int i    = rem & 31;

    float* p = (half ? k : q) + (size_t)row * DIM + head * DH;
    int pos = row & (SEQ - 1);

    float e = (2.0f * (float)i) / (float)DH;
    float theta = 1.0f / powf(1.0e6f, e);
    float angle = (float)pos * theta;
    float sn = sinf(angle);
    float cs = cosf(angle);

    float x1 = p[i];
    float x2 = p[i + 32];
    p[i]      = x1 * cs - x2 * sn;
    p[i + 32] = x1 * sn + x2 * cs;
}

// ===========================================================================
// Flash-style causal attention (fp32)
// ===========================================================================
__global__ __launch_bounds__(128) void flash_kernel(
    const float* __restrict__ q, const float* __restrict__ k,
    const float* __restrict__ v, float* __restrict__ o)
{
    __shared__ float Ks[32][64];
    __shared__ float Vs[32][64];

    int bh = blockIdx.y;
    int b  = bh >> 4;
    int h  = bh & 15;
    int qt = (gridDim.x - 1) - blockIdx.x;   // heavy tiles first
    int q0 = qt * 128;
    int tid = threadIdx.x;
    int qi = q0 + tid;

    const float* qrow = q + (size_t)(b * SEQ + qi) * DIM + h * DH;
    float qv[64];
    #pragma unroll
    for (int d = 0; d < 64; d += 4)
        *(float4*)&qv[d] = *(const float4*)&qrow[d];

    float acc[64];
    #pragma unroll
    for (int d = 0; d < 64; d++) acc[d] = 0.f;
    float l = 0.f;

    const float* kb = k + (size_t)b * SEQ * DIM + h * DH;
    const float* vb = v + (size_t)b * SEQ * DIM + h * DH;

    int ntiles = (q0 >> 5) + 4;

    for (int t = 0; t < ntiles; t++) {
        int k0 = t << 5;
        __syncthreads();
        #pragma unroll
        for (int f = tid; f < 512; f += 128) {
            int r = f >> 4;
            int c = (f & 15) << 2;
            *(float4*)&Ks[r][c] = *(const float4*)&kb[(size_t)(k0 + r) * DIM + c];
            *(float4*)&Vs[r][c] = *(const float4*)&vb[(size_t)(k0 + r) * DIM + c];
        }
        __syncthreads();

        for (int j = 0; j < 32; j++) {
            float s0 = 0.f, s1 = 0.f, s2 = 0.f, s3 = 0.f;
            #pragma unroll
            for (int d4 = 0; d4 < 16; d4++) {
                float4 kk = *(const float4*)&Ks[j][d4 * 4];
                s0 = fmaf(qv[d4 * 4 + 0], kk.x, s0);
                s1 = fmaf(qv[d4 * 4 + 1], kk.y, s1);
                s2 = fmaf(qv[d4 * 4 + 2], kk.z, s2);
                s3 = fmaf(qv[d4 * 4 + 3], kk.w, s3);
            }
            float sj = ((s0 + s1) + (s2 + s3)) * 0.125f;
            float p = (k0 + j <= qi) ? expf(sj) : 0.f;
            l += p;
            #pragma unroll
            for (int d4 = 0; d4 < 16; d4++) {
                float4 vv = *(const float4*)&Vs[j][d4 * 4];
                acc[d4 * 4 + 0] = fmaf(p, vv.x, acc[d4 * 4 + 0]);
                acc[d4 * 4 + 1] = fmaf(p, vv.y, acc[d4 * 4 + 1]);
                acc[d4 * 4 + 2] = fmaf(p, vv.z, acc[d4 * 4 + 2]);
                acc[d4 * 4 + 3] = fmaf(p, vv.w, acc[d4 * 4 + 3]);
            }
        }
    }

    float inv = 1.0f / l;
    float* orow = o + (size_t)(b * SEQ + qi) * DIM + h * DH;
    #pragma unroll
    for (int d = 0; d < 64; d += 4) {
        float4 vo = make_float4(acc[d] * inv, acc[d + 1] * inv,
                                acc[d + 2] * inv, acc[d + 3] * inv);
        *(float4*)&orow[d] = vo;
    }
}

// ===========================================================================
// Launch
// ===========================================================================
extern "C" void kernel_launch(void* const* d_in, const int* in_sizes, int n_in,
                              void* d_out, int out_size)
{
    (void)in_sizes; (void)n_in; (void)out_size;
    const float* x  = (const float*)d_in[0];
    const float* ns = (const float*)d_in[1];
    const float* Wq = (const float*)d_in[2];
    const float* Wk = (const float*)d_in[3];
    const float* Wv = (const float*)d_in[4];
    const float* Wo = (const float*)d_in[5];
    float* out = (float*)d_out;

    float *xn, *qb, *kb, *vb, *ao;
    __nv_bfloat16 *ah, *al, *th, *tl;
    cudaGetSymbolAddress((void**)&xn, g_xn);
    cudaGetSymbolAddress((void**)&qb, g_q);
    cudaGetSymbolAddress((void**)&kb, g_k);
    cudaGetSymbolAddress((void**)&vb, g_v);
    cudaGetSymbolAddress((void**)&ao, g_ao);
    cudaGetSymbolAddress((void**)&ah, g_ah);
    cudaGetSymbolAddress((void**)&al, g_al);
    cudaGetSymbolAddress((void**)&th, g_th);
    cudaGetSymbolAddress((void**)&tl, g_tl);

    cudaFuncSetAttribute(mma_gemm_kernel,
                         cudaFuncAttributeMaxDynamicSharedMemorySize, GEMM_SMEM);

    rmsnorm_kernel<<<ROWS, 256>>>(x, ns, xn);
    asplit_kernel<<<(ROWS * DIM) / (256 * 4), 256>>>(xn, ah, al);

    dim3 gg(DIM / 128, ROWS / 128);   // (8, 32)
    dim3 wg(DIM / 32, DIM / 32);      // (32, 32)

    wsplit_kernel<<<wg, 256>>>(Wq, th, tl);
    mma_gemm_kernel<<<gg, 256, GEMM_SMEM>>>(ah, al, th, tl, qb);
    wsplit_kernel<<<wg, 256>>>(Wk, th, tl);
    mma_gemm_kernel<<<gg, 256, GEMM_SMEM>>>(ah, al, th, tl, kb);
    wsplit_kernel<<<wg, 256>>>(Wv, th, tl);
    mma_gemm_kernel<<<gg, 256, GEMM_SMEM>>>(ah, al, th, tl, vb);

    rope_kernel<<<(2 * ROWS * NH * (DH / 2)) / 256, 256>>>(qb, kb);

    flash_kernel<<<dim3(SEQ / 128, BATCH * NH), 128>>>(qb, kb, vb, ao);

    asplit_kernel<<<(ROWS * DIM) / (256 * 4), 256>>>(ao, ah, al);
    wsplit_kernel<<<wg, 256>>>(Wo, th, tl);
    mma_gemm_kernel<<<gg, 256, GEMM_SMEM>>>(ah, al, th, tl, out);
}

// round 4
// speedup vs baseline: 3.2567x; 2.0684x over previous
#include <cuda_runtime.h>
#include <cuda_bf16.h>
#include <stdint.h>
#include <math.h>

#define BATCH 2
#define SEQ   2048
#define DIM   1024
#define ROWS  (BATCH*SEQ)   // 4096
#define NH    16
#define DH    64

// Scratch (allocation-free rule: __device__ globals)
__device__ float g_xn[ROWS*DIM];
__device__ float g_q [ROWS*DIM];
__device__ float g_k [ROWS*DIM];
__device__ float g_v [ROWS*DIM];
__device__ float g_ao[ROWS*DIM];
__device__ __nv_bfloat16 g_ah[ROWS*DIM];   // A split hi
__device__ __nv_bfloat16 g_al[ROWS*DIM];   // A split lo
__device__ __nv_bfloat16 g_th[DIM*DIM];    // W^T split hi  [N][K]
__device__ __nv_bfloat16 g_tl[DIM*DIM];    // W^T split lo  [N][K]
// attention operands, head-contiguous layouts
__device__ __nv_bfloat16 g_qh[ROWS*DIM];   // Q hi [bh][s][d]
__device__ __nv_bfloat16 g_ql[ROWS*DIM];   // Q lo
__device__ __nv_bfloat16 g_kh[ROWS*DIM];   // K hi [bh][s][d]
__device__ __nv_bfloat16 g_kl[ROWS*DIM];   // K lo
__device__ __nv_bfloat16 g_vth[ROWS*DIM];  // V^T hi [bh][d][s]
__device__ __nv_bfloat16 g_vtl[ROWS*DIM];  // V^T lo

// ===========================================================================
// Portable (compute_103-safe) PTX helpers: mma.sync / ldmatrix / cp.async
// ===========================================================================
__device__ __forceinline__ uint32_t smem_u32(const void* p) {
    uint32_t a;
    asm("{ .reg .u64 t; cvta.to.shared.u64 t, %1; cvt.u32.u64 %0, t; }"
        : "=r"(a) : "l"(p));
    return a;
}
__device__ __forceinline__ void cp_async16(uint32_t saddr, const void* gaddr) {
    asm volatile("cp.async.cg.shared.global [%0], [%1], 16;"
                 :: "r"(saddr), "l"(gaddr));
}
__device__ __forceinline__ void cp_commit() {
    asm volatile("cp.async.commit_group;" ::: "memory");
}
__device__ __forceinline__ void ldsm4(uint32_t* r, uint32_t addr) {
    asm volatile("ldmatrix.sync.aligned.m8n8.x4.shared.b16 {%0,%1,%2,%3}, [%4];"
                 : "=r"(r[0]), "=r"(r[1]), "=r"(r[2]), "=r"(r[3]) : "r"(addr));
}
__device__ __forceinline__ void mma16816(float* c, const uint32_t* a,
                                         uint32_t b0, uint32_t b1) {
    asm volatile(
        "mma.sync.aligned.m16n8k16.row.col.f32.bf16.bf16.f32 "
        "{%0,%1,%2,%3}, {%4,%5,%6,%7}, {%8,%9}, {%0,%1,%2,%3};"
        : "+f"(c[0]), "+f"(c[1]), "+f"(c[2]), "+f"(c[3])
        : "r"(a[0]), "r"(a[1]), "r"(a[2]), "r"(a[3]), "r"(b0), "r"(b1));
}
__device__ __forceinline__ uint32_t pack2h(__nv_bfloat16 a, __nv_bfloat16 b) {
    __nv_bfloat162 t = __halves2bfloat162(a, b);
    return *reinterpret_cast<uint32_t*>(&t);
}
__device__ __forceinline__ uint32_t pack2f(float a, float b) {
    __nv_bfloat162 t = __floats2bfloat162_rn(a, b);
    return *reinterpret_cast<uint32_t*>(&t);
}

// ===========================================================================
// RMSNorm: one block per row
// ===========================================================================
__global__ __launch_bounds__(256) void rmsnorm_kernel(
    const float* __restrict__ x, const float* __restrict__ sc,
    float* __restrict__ y)
{
    int row = blockIdx.x;
    const float* xr = x + (size_t)row * DIM;
    float ss = 0.f;
    #pragma unroll
    for (int i = threadIdx.x; i < DIM; i += 256) {
        float v = xr[i];
        ss = fmaf(v, v, ss);
    }
    __shared__ float red[256];
    red[threadIdx.x] = ss;
    __syncthreads();
    #pragma unroll
    for (int s = 128; s > 0; s >>= 1) {
        if (threadIdx.x < s) red[threadIdx.x] += red[threadIdx.x + s];
        __syncthreads();
    }
    float r = rsqrtf(red[0] * (1.0f / DIM) + 1e-6f);
    float* yr = y + (size_t)row * DIM;
    #pragma unroll
    for (int i = threadIdx.x; i < DIM; i += 256)
        yr[i] = xr[i] * r * sc[i];
}

// ===========================================================================
// Split fp32 -> bf16 (hi, lo). One thread per 4 elements.
// ===========================================================================
__global__ __launch_bounds__(256) void asplit_kernel(
    const float* __restrict__ x,
    __nv_bfloat16* __restrict__ hi, __nv_bfloat16* __restrict__ lo)
{
    int i = (blockIdx.x * 256 + threadIdx.x) * 4;
    float4 v = *(const float4*)(x + i);
    __nv_bfloat16 h0 = __float2bfloat16(v.x);
    __nv_bfloat16 h1 = __float2bfloat16(v.y);
    __nv_bfloat16 h2 = __float2bfloat16(v.z);
    __nv_bfloat16 h3 = __float2bfloat16(v.w);
    *(__nv_bfloat162*)(hi + i)     = __halves2bfloat162(h0, h1);
    *(__nv_bfloat162*)(hi + i + 2) = __halves2bfloat162(h2, h3);
    __nv_bfloat16 l0 = __float2bfloat16(v.x - __bfloat162float(h0));
    __nv_bfloat16 l1 = __float2bfloat16(v.y - __bfloat162float(h1));
    __nv_bfloat16 l2 = __float2bfloat16(v.z - __bfloat162float(h2));
    __nv_bfloat16 l3 = __float2bfloat16(v.w - __bfloat162float(h3));
    *(__nv_bfloat162*)(lo + i)     = __halves2bfloat162(l0, l1);
    *(__nv_bfloat162*)(lo + i + 2) = __halves2bfloat162(l2, l3);
}

// ===========================================================================
// Transpose + split: W [K=1024][N=1024] fp32 -> T_hi/T_lo [N][K] bf16
// ===========================================================================
__global__ __launch_bounds__(256) void wsplit_kernel(
    const float* __restrict__ W,
    __nv_bfloat16* __restrict__ Th, __nv_bfloat16* __restrict__ Tl)
{
    __shared__ float tile[32][33];
    int k0 = blockIdx.y * 32, n0 = blockIdx.x * 32;
    int tx = threadIdx.x & 31, ty = threadIdx.x >> 5;   // 32 x 8
    #pragma unroll
    for (int i = 0; i < 32; i += 8)
        tile[ty + i][tx] = W[(size_t)(k0 + ty + i) * DIM + n0 + tx];
    __syncthreads();
    #pragma unroll
    for (int i = 0; i < 32; i += 8) {
        float v = tile[tx][ty + i];    // = W[k0+tx][n0+ty+i]
        __nv_bfloat16 h = __float2bfloat16(v);
        float r = v - __bfloat162float(h);
        size_t o = (size_t)(n0 + ty + i) * DIM + k0 + tx;
        Th[o] = h;
        Tl[o] = __float2bfloat16(r);
    }
}

// ===========================================================================
// bf16-split GEMM via mma.sync (validated round 3)
// ===========================================================================
#define TILE_B  10240              // 128 rows x 80 bytes
#define STAGE_B (4*TILE_B)         // Ah,Al,Bh,Bl
#define GEMM_SMEM (2*STAGE_B)      // 81920

__global__ __launch_bounds__(256) void mma_gemm_kernel(
    const __nv_bfloat16* __restrict__ Ah, const __nv_bfloat16* __restrict__ Al,
    const __nv_bfloat16* __restrict__ Bh, const __nv_bfloat16* __restrict__ Bl,
    float* __restrict__ C)
{
    extern __shared__ char smem[];
    uint32_t sb = smem_u32(smem);

    const int tid  = threadIdx.x;
    const int lane = tid & 31;
    const int wid  = tid >> 5;
    const int warp_m = wid & 3;
    const int warp_n = wid >> 2;
    const int bm = blockIdx.y * 128;
    const int bn = blockIdx.x * 128;

    const __nv_bfloat16* gsrc[4] = {Ah, Al, Bh, Bl};

    float acc[2][8][4];
    #pragma unroll
    for (int i = 0; i < 2; i++)
        #pragma unroll
        for (int j = 0; j < 8; j++)
            #pragma unroll
            for (int q = 0; q < 4; q++) acc[i][j][q] = 0.f;

    auto load_stage = [&](int kt, int s) {
        #pragma unroll
        for (int t = 0; t < 4; t++) {
            const __nv_bfloat16* src = gsrc[t];
            int row0 = (t < 2) ? bm : bn;
            #pragma unroll
            for (int i = 0; i < 2; i++) {
                int chunk = tid + i * 256;
                int row = chunk >> 2;
                int c   = chunk & 3;
                const void* g = src + (size_t)(row0 + row) * DIM + kt * 32 + c * 8;
                uint32_t sa = sb + s * STAGE_B + t * TILE_B + row * 80 + c * 16;
                cp_async16(sa, g);
            }
        }
        cp_commit();
    };

    load_stage(0, 0);
    load_stage(1, 1);

    const int aRow = lane & 15;
    const int aK16 = (lane >> 4) * 16;
    const int bRow = (lane & 7) + ((lane >> 4) << 3);
    const int bK16 = ((lane >> 3) & 1) * 16;

    for (int kt = 0; kt < 32; kt++) {
        if (kt < 31) asm volatile("cp.async.wait_group 1;" ::: "memory");
        else         asm volatile("cp.async.wait_group 0;" ::: "memory");
        __syncthreads();

        uint32_t st = sb + (kt & 1) * STAGE_B;
        uint32_t aH = st + 0 * TILE_B + (warp_m * 32 + aRow) * 80 + aK16;
        uint32_t aL = st + 1 * TILE_B + (warp_m * 32 + aRow) * 80 + aK16;
        uint32_t bH = st + 2 * TILE_B + (warp_n * 64 + bRow) * 80 + bK16;
        uint32_t bL = st + 3 * TILE_B + (warp_n * 64 + bRow) * 80 + bK16;

        #pragma unroll
        for (int ks = 0; ks < 2; ks++) {
            uint32_t koff = ks * 32;
            uint32_t fah[2][4], fal[2][4], fbh[4][4], fbl[4][4];
            #pragma unroll
            for (int mt = 0; mt < 2; mt++) {
                ldsm4(fah[mt], aH + mt * 16 * 80 + koff);
                ldsm4(fal[mt], aL + mt * 16 * 80 + koff);
            }
            #pragma unroll
            for (int nt2 = 0; nt2 < 4; nt2++) {
                ldsm4(fbh[nt2], bH + nt2 * 16 * 80 + koff);
                ldsm4(fbl[nt2], bL + nt2 * 16 * 80 + koff);
            }
            #pragma unroll
            for (int mt = 0; mt < 2; mt++)
                #pragma unroll
                for (int nt = 0; nt < 8; nt++)
                    mma16816(acc[mt][nt], fah[mt],
                             fbh[nt >> 1][(nt & 1) * 2], fbh[nt >> 1][(nt & 1) * 2 + 1]);
            #pragma unroll
            for (int mt = 0; mt < 2; mt++)
                #pragma unroll
                for (int nt = 0; nt < 8; nt++)
                    mma16816(acc[mt][nt], fah[mt],
                             fbl[nt >> 1][(nt & 1) * 2], fbl[nt >> 1][(nt & 1) * 2 + 1]);
            #pragma unroll
            for (int mt = 0; mt < 2; mt++)
                #pragma unroll
                for (int nt = 0; nt < 8; nt++)
                    mma16816(acc[mt][nt], fal[mt],
                             fbh[nt >> 1][(nt & 1) * 2], fbh[nt >> 1][(nt & 1) * 2 + 1]);
        }
        __syncthreads();
        if (kt + 2 < 32) load_stage(kt + 2, kt & 1);
    }

    const int g = lane >> 2, t2 = (lane & 3) * 2;
    #pragma unroll
    for (int mt = 0; mt < 2; mt++) {
        #pragma unroll
        for (int nt = 0; nt < 8; nt++) {
            int row = bm + warp_m * 32 + mt * 16 + g;
            int col = bn + warp_n * 64 + nt * 8 + t2;
            *(float2*)&C[(size_t)row * DIM + col] =
                make_float2(acc[mt][nt][0], acc[mt][nt][1]);
            *(float2*)&C[(size_t)(row + 8) * DIM + col] =
                make_float2(acc[mt][nt][2], acc[mt][nt][3]);
        }
    }
}

// ===========================================================================
// RoPE + split + relayout: q,k fp32 [row][h*64+d] -> bf16 hi/lo [bh][s][d]
// ===========================================================================
__global__ __launch_bounds__(256) void rope_split_kernel(
    const float* __restrict__ q, const float* __restrict__ k,
    __nv_bfloat16* __restrict__ Qh, __nv_bfloat16* __restrict__ Ql,
    __nv_bfloat16* __restrict__ Kh, __nv_bfloat16* __restrict__ Kl)
{
    int idx = blockIdx.x * 256 + threadIdx.x;   // 2^22 total
    int which = idx >> 21;
    int r   = idx & ((1 << 21) - 1);
    int row = r >> 9;
    int rem = r & 511;
    int head = rem >> 5;
    int i    = rem & 31;

    const float* src = (which ? k : q) + (size_t)row * DIM + head * DH;
    int pos = row & (SEQ - 1);

    float e = (2.0f * (float)i) / (float)DH;
    float theta = powf(1.0e6f, -e);
    float ang = (float)pos * theta;
    float sn = sinf(ang), cs = cosf(ang);

    float x1 = src[i], x2 = src[i + 32];
    float y1 = x1 * cs - x2 * sn;
    float y2 = x1 * sn + x2 * cs;

    int b = row >> 11, s = row & (SEQ - 1);
    size_t o = ((size_t)(b * NH + head) * SEQ + s) * DH + i;
    __nv_bfloat16 h1 = __float2bfloat16(y1);
    __nv_bfloat16 h2 = __float2bfloat16(y2);
    __nv_bfloat16* H = which ? Kh : Qh;
    __nv_bfloat16* L = which ? Kl : Ql;
    H[o]      = h1;
    H[o + 32] = h2;
    L[o]      = __float2bfloat16(y1 - __bfloat162float(h1));
    L[o + 32] = __float2bfloat16(y2 - __bfloat162float(h2));
}

// ===========================================================================
// V transpose + split: v fp32 [row][h*64+d] -> bf16 hi/lo [bh][d][s]
// ===========================================================================
__global__ __launch_bounds__(256) void vsplit_kernel(
    const float* __restrict__ v,
    __nv_bfloat16* __restrict__ Vth, __nv_bfloat16* __restrict__ Vtl)
{
    __shared__ float tile[32][33];
    int bh = blockIdx.z;
    int b = bh >> 4, h = bh & 15;
    int s0 = blockIdx.x * 32, d0 = blockIdx.y * 32;
    int tx = threadIdx.x & 31, ty = threadIdx.x >> 5;
    #pragma unroll
    for (int i = 0; i < 32; i += 8)
        tile[ty + i][tx] = v[(size_t)(b * SEQ + s0 + ty + i) * DIM + h * DH + d0 + tx];
    __syncthreads();
    #pragma unroll
    for (int i = 0; i < 32; i += 8) {
        float val = tile[tx][ty + i];   // = v[s0+tx][d0+ty+i]
        __nv_bfloat16 hh = __float2bfloat16(val);
        size_t o = ((size_t)(bh * DH + d0 + ty + i)) * SEQ + s0 + tx;
        Vth[o] = hh;
        Vtl[o] = __float2bfloat16(val - __bfloat162float(hh));
    }
}

// ===========================================================================
// Flash attention via mma.sync, split-bf16 throughout.
// Block: 128 q-rows x one (b,h). 8 warps x 16 rows. K-chunks of 64 keys,
// cp.async double buffered. Q resident in registers.
// ===========================================================================
#define FP      144                 // smem row pitch (bytes)
#define FQ_OFF  0                   // Qh @0, Ql @18432 (128 rows x 144)
#define FK_OFF  36864               // + stage*18432; Kh +0, Kl +9216 (64x144)
#define FV_OFF  73728               // + stage*18432; Vh +0, Vl +9216 (64x144)
#define FL_SMEM 110592

__global__ __launch_bounds__(256) void flash_mma_kernel(
    const __nv_bfloat16* __restrict__ Qh_, const __nv_bfloat16* __restrict__ Ql_,
    const __nv_bfloat16* __restrict__ Kh_, const __nv_bfloat16* __restrict__ Kl_,
    const __nv_bfloat16* __restrict__ Vth_, const __nv_bfloat16* __restrict__ Vtl_,
    float* __restrict__ ao)
{
    extern __shared__ char smem[];
    uint32_t sb = smem_u32(smem);
    const int tid = threadIdx.x, lane = tid & 31, wid = tid >> 5;
    const int bh = blockIdx.y;
    const int qt = (gridDim.x - 1) - blockIdx.x;   // heavy tiles first
    const int nkt = 2 * (qt + 1);                  // 64-key chunks
    const size_t qkoff = (size_t)bh * SEQ * DH;
    const size_t voff  = (size_t)bh * DH * SEQ;

    // Q tile load (once)
    {
        const __nv_bfloat16* qs[2] = {Qh_ + qkoff, Ql_ + qkoff};
        #pragma unroll
        for (int i = 0; i < 8; i++) {
            int idx = tid + i * 256;           // 0..2047
            int t = idx >> 10, rem = idx & 1023;
            int row = rem >> 3, c = rem & 7;
            cp_async16(sb + FQ_OFF + t * 18432 + row * FP + c * 16,
                       qs[t] + (size_t)(qt * 128 + row) * DH + c * 8);
        }
        cp_commit();
    }

    auto load_kv = [&](int kt, int s) {
        int k0 = kt * 64;
        const __nv_bfloat16* ks_[2] = {Kh_ + qkoff, Kl_ + qkoff};
        const __nv_bfloat16* vs_[2] = {Vth_ + voff, Vtl_ + voff};
        #pragma unroll
        for (int i = 0; i < 4; i++) {
            int idx = tid + i * 256;           // 0..1023
            int t = idx >> 9, rem = idx & 511;
            int row = rem >> 3, c = rem & 7;
            cp_async16(sb + FK_OFF + s * 18432 + t * 9216 + row * FP + c * 16,
                       ks_[t] + (size_t)(k0 + row) * DH + c * 8);
        }
        #pragma unroll
        for (int i = 0; i < 4; i++) {
            int idx = tid + i * 256;
            int t = idx >> 9, rem = idx & 511;
            int row = rem >> 3, c = rem & 7;   // row = dh index, c = key chunk
            cp_async16(sb + FV_OFF + s * 18432 + t * 9216 + row * FP + c * 16,
                       vs_[t] + (size_t)row * SEQ + k0 + c * 8);
        }
        cp_commit();
    };
    load_kv(0, 0);
    load_kv(1, 1);

    const int g = lane >> 2, t2 = (lane & 3) * 2;
    const int aRow = lane & 15, aK16 = (lane >> 4) * 16;
    const int bRow = (lane & 7) + ((lane >> 4) << 3);
    const int bK16 = ((lane >> 3) & 1) * 16;

    asm volatile("cp.async.wait_group 2;" ::: "memory");
    __syncthreads();

    // Q fragments resident: 4 k-steps x (hi, lo)
    uint32_t qh[4][4], ql[4][4];
    {
        uint32_t base = sb + FQ_OFF + (wid * 16 + aRow) * FP + aK16;
        #pragma unroll
        for (int ks = 0; ks < 4; ks++) {
            ldsm4(qh[ks], base + ks * 32);
            ldsm4(ql[ks], base + 18432 + ks * 32);
        }
    }

    float o[8][4];
    #pragma unroll
    for (int nt = 0; nt < 8; nt++)
        #pragma unroll
        for (int j = 0; j < 4; j++) o[nt][j] = 0.f;
    float l0 = 0.f, l1 = 0.f;
    const int row0 = qt * 128 + wid * 16 + g;

    for (int kt = 0; kt < nkt; kt++) {
        if (kt < nkt - 1) asm volatile("cp.async.wait_group 1;" ::: "memory");
        else              asm volatile("cp.async.wait_group 0;" ::: "memory");
        __syncthreads();

        uint32_t stK = sb + FK_OFF + (kt & 1) * 18432;
        uint32_t stV = sb + FV_OFF + (kt & 1) * 18432;

        // ---- S = Q K^T (3-way split) ----
        float S[8][4];
        #pragma unroll
        for (int nt = 0; nt < 8; nt++)
            #pragma unroll
            for (int j = 0; j < 4; j++) S[nt][j] = 0.f;

        #pragma unroll
        for (int ks = 0; ks < 4; ks++) {
            uint32_t fkh[4][4], fkl[4][4];
            #pragma unroll
            for (int n2 = 0; n2 < 4; n2++) {
                uint32_t a = stK + (n2 * 16 + bRow) * FP + bK16 + ks * 32;
                ldsm4(fkh[n2], a);
                ldsm4(fkl[n2], a + 9216);
            }
            #pragma unroll
            for (int nt = 0; nt < 8; nt++) {
                mma16816(S[nt], qh[ks], fkh[nt >> 1][(nt & 1) * 2], fkh[nt >> 1][(nt & 1) * 2 + 1]);
                mma16816(S[nt], qh[ks], fkl[nt >> 1][(nt & 1) * 2], fkl[nt >> 1][(nt & 1) * 2 + 1]);
                mma16816(S[nt], ql[ks], fkh[nt >> 1][(nt & 1) * 2], fkh[nt >> 1][(nt & 1) * 2 + 1]);
            }
        }

        // ---- softmax (no-max) + pack P into A-fragments ----
        uint32_t pah[4][4], pal[4][4];
        int k0 = kt * 64;
        #pragma unroll
        for (int nt = 0; nt < 8; nt++) {
            int col = k0 + nt * 8 + t2;
            float p0 = (col     <= row0)     ? __expf(S[nt][0] * 0.125f) : 0.f;
            float p1 = (col + 1 <= row0)     ? __expf(S[nt][1] * 0.125f) : 0.f;
            float p2 = (col     <= row0 + 8) ? __expf(S[nt][2] * 0.125f) : 0.f;
            float p3 = (col + 1 <= row0 + 8) ? __expf(S[nt][3] * 0.125f) : 0.f;
            l0 += p0 + p1;
            l1 += p2 + p3;
            __nv_bfloat16 h0 = __float2bfloat16(p0), h1 = __float2bfloat16(p1);
            __nv_bfloat16 h2 = __float2bfloat16(p2), h3 = __float2bfloat16(p3);
            float r0 = p0 - __bfloat162float(h0), r1 = p1 - __bfloat162float(h1);
            float r2 = p2 - __bfloat162float(h2), r3 = p3 - __bfloat162float(h3);
            int ks2 = nt >> 1, off = (nt & 1) * 2;
            pah[ks2][off]     = pack2h(h0, h1);
            pah[ks2][off + 1] = pack2h(h2, h3);
            pal[ks2][off]     = pack2f(r0, r1);
            pal[ks2][off + 1] = pack2f(r2, r3);
        }

        // ---- O += P V (3-way split), V^T in smem as [dh][key] ----
        #pragma unroll
        for (int ks2 = 0; ks2 < 4; ks2++) {
            uint32_t fvh[4][4], fvl[4][4];
            #pragma unroll
            for (int n2 = 0; n2 < 4; n2++) {
                uint32_t a = stV + (n2 * 16 + bRow) * FP + bK16 + ks2 * 32;
                ldsm4(fvh[n2], a);
                ldsm4(fvl[n2], a + 9216);
            }
            #pragma unroll
            for (int nt = 0; nt < 8; nt++) {
                mma16816(o[nt], pah[ks2], fvh[nt >> 1][(nt & 1) * 2], fvh[nt >> 1][(nt & 1) * 2 + 1]);
                mma16816(o[nt], pah[ks2], fvl[nt >> 1][(nt & 1) * 2], fvl[nt >> 1][(nt & 1) * 2 + 1]);
                mma16816(o[nt], pal[ks2], fvh[nt >> 1][(nt & 1) * 2], fvh[nt >> 1][(nt & 1) * 2 + 1]);
            }
        }

        __syncthreads();
        if (kt + 2 < nkt) load_kv(kt + 2, kt & 1);
    }

    // row-sum reduce within quads (lanes sharing g)
    l0 += __shfl_xor_sync(0xFFFFFFFFu, l0, 1);
    l0 += __shfl_xor_sync(0xFFFFFFFFu, l0, 2);
    l1 += __shfl_xor_sync(0xFFFFFFFFu, l1, 1);
    l1 += __shfl_xor_sync(0xFFFFFFFFu, l1, 2);
    float inv0 = 1.0f / l0, inv1 = 1.0f / l1;

    int b = bh >> 4, h = bh & 15;
    int srow = qt * 128 + wid * 16 + g;
    #pragma unroll
    for (int nt = 0; nt < 8; nt++) {
        int d = nt * 8 + t2;
        size_t o0 = (size_t)(b * SEQ + srow) * DIM + h * DH + d;
        size_t o1 = (size_t)(b * SEQ + srow + 8) * DIM + h * DH + d;
        *(float2*)&ao[o0] = make_float2(o[nt][0] * inv0, o[nt][1] * inv0);
        *(float2*)&ao[o1] = make_float2(o[nt][2] * inv1, o[nt][3] * inv1);
    }
}

// ===========================================================================
// Launch
// ===========================================================================
extern "C" void kernel_launch(void* const* d_in, const int* in_sizes, int n_in,
                              void* d_out, int out_size)
{
    (void)in_sizes; (void)n_in; (void)out_size;
    const float* x  = (const float*)d_in[0];
    const float* ns = (const float*)d_in[1];
    const float* Wq = (const float*)d_in[2];
    const float* Wk = (const float*)d_in[3];
    const float* Wv = (const float*)d_in[4];
    const float* Wo = (const float*)d_in[5];
    float* out = (float*)d_out;

    float *xn, *qb, *kb, *vb, *ao;
    __nv_bfloat16 *ah, *al, *th, *tl, *qhp, *qlp, *khp, *klp, *vth, *vtl;
    cudaGetSymbolAddress((void**)&xn, g_xn);
    cudaGetSymbolAddress((void**)&qb, g_q);
    cudaGetSymbolAddress((void**)&kb, g_k);
    cudaGetSymbolAddress((void**)&vb, g_v);
    cudaGetSymbolAddress((void**)&ao, g_ao);
    cudaGetSymbolAddress((void**)&ah, g_ah);
    cudaGetSymbolAddress((void**)&al, g_al);
    cudaGetSymbolAddress((void**)&th, g_th);
    cudaGetSymbolAddress((void**)&tl, g_tl);
    cudaGetSymbolAddress((void**)&qhp, g_qh);
    cudaGetSymbolAddress((void**)&qlp, g_ql);
    cudaGetSymbolAddress((void**)&khp, g_kh);
    cudaGetSymbolAddress((void**)&klp, g_kl);
    cudaGetSymbolAddress((void**)&vth, g_vth);
    cudaGetSymbolAddress((void**)&vtl, g_vtl);

    cudaFuncSetAttribute(mma_gemm_kernel,
                         cudaFuncAttributeMaxDynamicSharedMemorySize, GEMM_SMEM);
    cudaFuncSetAttribute(flash_mma_kernel,
                         cudaFuncAttributeMaxDynamicSharedMemorySize, FL_SMEM);

    rmsnorm_kernel<<<ROWS, 256>>>(x, ns, xn);
    asplit_kernel<<<(ROWS * DIM) / (256 * 4), 256>>>(xn, ah, al);

    dim3 gg(DIM / 128, ROWS / 128);   // (8, 32)
    dim3 wg(DIM / 32, DIM / 32);      // (32, 32)

    wsplit_kernel<<<wg, 256>>>(Wq, th, tl);
    mma_gemm_kernel<<<gg, 256, GEMM_SMEM>>>(ah, al, th, tl, qb);
    wsplit_kernel<<<wg, 256>>>(Wk, th, tl);
    mma_gemm_kernel<<<gg, 256, GEMM_SMEM>>>(ah, al, th, tl, kb);
    wsplit_kernel<<<wg, 256>>>(Wv, th, tl);
    mma_gemm_kernel<<<gg, 256, GEMM_SMEM>>>(ah, al, th, tl, vb);

    rope_split_kernel<<<(2 * ROWS * NH * 32) / 256, 256>>>(qb, kb, qhp, qlp, khp, klp);
    vsplit_kernel<<<dim3(SEQ / 32, DH / 32, BATCH * NH), 256>>>(vb, vth, vtl);

    flash_mma_kernel<<<dim3(SEQ / 128, BATCH * NH), 256, FL_SMEM>>>(
        qhp, qlp, khp, klp, vth, vtl, ao);

    asplit_kernel<<<(ROWS * DIM) / (256 * 4), 256>>>(ao, ah, al);
    wsplit_kernel<<<wg, 256>>>(Wo, th, tl);
    mma_gemm_kernel<<<gg, 256, GEMM_SMEM>>>(ah, al, th, tl, out);
}

// round 5
// speedup vs baseline: 3.3360x; 1.0243x over previous
#include <cuda_runtime.h>
#include <cuda_bf16.h>
#include <stdint.h>
#include <math.h>

#define BATCH 2
#define SEQ   2048
#define DIM   1024
#define ROWS  (BATCH*SEQ)   // 4096
#define NH    16
#define DH    64

// Scratch (allocation-free rule: __device__ globals)
__device__ float g_xn[ROWS*DIM];
__device__ float g_q [ROWS*DIM];
__device__ float g_k [ROWS*DIM];
__device__ float g_v [ROWS*DIM];
__device__ float g_ao[ROWS*DIM];
__device__ __nv_bfloat16 g_ah[ROWS*DIM];   // A split hi
__device__ __nv_bfloat16 g_al[ROWS*DIM];   // A split lo
__device__ __nv_bfloat16 g_th[DIM*DIM];    // W^T split hi  [N][K]
__device__ __nv_bfloat16 g_tl[DIM*DIM];    // W^T split lo  [N][K]
// attention operands, head-contiguous layouts
__device__ __nv_bfloat16 g_qh[ROWS*DIM];   // Q hi [bh][s][d]
__device__ __nv_bfloat16 g_ql[ROWS*DIM];   // Q lo
__device__ __nv_bfloat16 g_kh[ROWS*DIM];   // K hi [bh][s][d]
__device__ __nv_bfloat16 g_kl[ROWS*DIM];   // K lo
__device__ __nv_bfloat16 g_vth[ROWS*DIM];  // V^T hi [bh][d][s]
__device__ __nv_bfloat16 g_vtl[ROWS*DIM];  // V^T lo

// ===========================================================================
// Portable (compute_103-safe) PTX helpers: mma.sync / ldmatrix / cp.async
// ===========================================================================
__device__ __forceinline__ uint32_t smem_u32(const void* p) {
    uint32_t a;
    asm("{ .reg .u64 t; cvta.to.shared.u64 t, %1; cvt.u32.u64 %0, t; }"
        : "=r"(a) : "l"(p));
    return a;
}
__device__ __forceinline__ void cp_async16(uint32_t saddr, const void* gaddr) {
    asm volatile("cp.async.cg.shared.global [%0], [%1], 16;"
                 :: "r"(saddr), "l"(gaddr));
}
__device__ __forceinline__ void cp_commit() {
    asm volatile("cp.async.commit_group;" ::: "memory");
}
__device__ __forceinline__ void ldsm4(uint32_t* r, uint32_t addr) {
    asm volatile("ldmatrix.sync.aligned.m8n8.x4.shared.b16 {%0,%1,%2,%3}, [%4];"
                 : "=r"(r[0]), "=r"(r[1]), "=r"(r[2]), "=r"(r[3]) : "r"(addr));
}
__device__ __forceinline__ void mma16816(float* c, const uint32_t* a,
                                         uint32_t b0, uint32_t b1) {
    asm volatile(
        "mma.sync.aligned.m16n8k16.row.col.f32.bf16.bf16.f32 "
        "{%0,%1,%2,%3}, {%4,%5,%6,%7}, {%8,%9}, {%0,%1,%2,%3};"
        : "+f"(c[0]), "+f"(c[1]), "+f"(c[2]), "+f"(c[3])
        : "r"(a[0]), "r"(a[1]), "r"(a[2]), "r"(a[3]), "r"(b0), "r"(b1));
}
__device__ __forceinline__ uint32_t pack2h(__nv_bfloat16 a, __nv_bfloat16 b) {
    __nv_bfloat162 t = __halves2bfloat162(a, b);
    return *reinterpret_cast<uint32_t*>(&t);
}
__device__ __forceinline__ uint32_t pack2f(float a, float b) {
    __nv_bfloat162 t = __floats2bfloat162_rn(a, b);
    return *reinterpret_cast<uint32_t*>(&t);
}

// ===========================================================================
// RMSNorm: one block per row
// ===========================================================================
__global__ __launch_bounds__(256) void rmsnorm_kernel(
    const float* __restrict__ x, const float* __restrict__ sc,
    float* __restrict__ y)
{
    int row = blockIdx.x;
    const float* xr = x + (size_t)row * DIM;
    float ss = 0.f;
    #pragma unroll
    for (int i = threadIdx.x; i < DIM; i += 256) {
        float v = xr[i];
        ss = fmaf(v, v, ss);
    }
    __shared__ float red[256];
    red[threadIdx.x] = ss;
    __syncthreads();
    #pragma unroll
    for (int s = 128; s > 0; s >>= 1) {
        if (threadIdx.x < s) red[threadIdx.x] += red[threadIdx.x + s];
        __syncthreads();
    }
    float r = rsqrtf(red[0] * (1.0f / DIM) + 1e-6f);
    float* yr = y + (size_t)row * DIM;
    #pragma unroll
    for (int i = threadIdx.x; i < DIM; i += 256)
        yr[i] = xr[i] * r * sc[i];
}

// ===========================================================================
// Split fp32 -> bf16 (hi, lo). One thread per 4 elements.
// ===========================================================================
__global__ __launch_bounds__(256) void asplit_kernel(
    const float* __restrict__ x,
    __nv_bfloat16* __restrict__ hi, __nv_bfloat16* __restrict__ lo)
{
    int i = (blockIdx.x * 256 + threadIdx.x) * 4;
    float4 v = *(const float4*)(x + i);
    __nv_bfloat16 h0 = __float2bfloat16(v.x);
    __nv_bfloat16 h1 = __float2bfloat16(v.y);
    __nv_bfloat16 h2 = __float2bfloat16(v.z);
    __nv_bfloat16 h3 = __float2bfloat16(v.w);
    *(__nv_bfloat162*)(hi + i)     = __halves2bfloat162(h0, h1);
    *(__nv_bfloat162*)(hi + i + 2) = __halves2bfloat162(h2, h3);
    __nv_bfloat16 l0 = __float2bfloat16(v.x - __bfloat162float(h0));
    __nv_bfloat16 l1 = __float2bfloat16(v.y - __bfloat162float(h1));
    __nv_bfloat16 l2 = __float2bfloat16(v.z - __bfloat162float(h2));
    __nv_bfloat16 l3 = __float2bfloat16(v.w - __bfloat162float(h3));
    *(__nv_bfloat162*)(lo + i)     = __halves2bfloat162(l0, l1);
    *(__nv_bfloat162*)(lo + i + 2) = __halves2bfloat162(l2, l3);
}

// ===========================================================================
// Transpose + split: W [K=1024][N=1024] fp32 -> T_hi/T_lo [N][K] bf16
// ===========================================================================
__global__ __launch_bounds__(256) void wsplit_kernel(
    const float* __restrict__ W,
    __nv_bfloat16* __restrict__ Th, __nv_bfloat16* __restrict__ Tl)
{
    __shared__ float tile[32][33];
    int k0 = blockIdx.y * 32, n0 = blockIdx.x * 32;
    int tx = threadIdx.x & 31, ty = threadIdx.x >> 5;   // 32 x 8
    #pragma unroll
    for (int i = 0; i < 32; i += 8)
        tile[ty + i][tx] = W[(size_t)(k0 + ty + i) * DIM + n0 + tx];
    __syncthreads();
    #pragma unroll
    for (int i = 0; i < 32; i += 8) {
        float v = tile[tx][ty + i];    // = W[k0+tx][n0+ty+i]
        __nv_bfloat16 h = __float2bfloat16(v);
        float r = v - __bfloat162float(h);
        size_t o = (size_t)(n0 + ty + i) * DIM + k0 + tx;
        Th[o] = h;
        Tl[o] = __float2bfloat16(r);
    }
}

// ===========================================================================
// bf16-split GEMM via mma.sync. Block tile 256x128, BK=32, 8 warps (4x2),
// warp tile 64x64. B-frag registers reused across hi/lo passes to cap
// pressure: (AhBh + AlBh) with fbh, then AhBl with fbl.
// ===========================================================================
#define A_TILE_B 20480             // 256 rows x 80 bytes
#define B_TILE_B 10240             // 128 rows x 80 bytes
#define STG_B    (2*A_TILE_B + 2*B_TILE_B)   // 61440
#define GEMM_SMEM (2*STG_B)                   // 122880

__global__ __launch_bounds__(256) void mma_gemm_kernel(
    const __nv_bfloat16* __restrict__ Ah, const __nv_bfloat16* __restrict__ Al,
    const __nv_bfloat16* __restrict__ Bh, const __nv_bfloat16* __restrict__ Bl,
    float* __restrict__ C)
{
    extern __shared__ char smem[];
    uint32_t sb = smem_u32(smem);

    const int tid  = threadIdx.x;
    const int lane = tid & 31;
    const int wid  = tid >> 5;
    const int warp_m = wid & 3;        // 4 slabs of 64 rows
    const int warp_n = wid >> 2;       // 2 slabs of 64 cols
    const int bm = blockIdx.y * 256;
    const int bn = blockIdx.x * 128;

    float acc[4][8][4];
    #pragma unroll
    for (int i = 0; i < 4; i++)
        #pragma unroll
        for (int j = 0; j < 8; j++)
            #pragma unroll
            for (int q = 0; q < 4; q++) acc[i][j][q] = 0.f;

    auto load_stage = [&](int kt, int s) {
        const __nv_bfloat16* asrc[2] = {Ah, Al};
        #pragma unroll
        for (int t = 0; t < 2; t++) {
            #pragma unroll
            for (int i = 0; i < 4; i++) {
                int chunk = tid + i * 256;         // 0..1023
                int row = chunk >> 2, c = chunk & 3;
                cp_async16(sb + s * STG_B + t * A_TILE_B + row * 80 + c * 16,
                           asrc[t] + (size_t)(bm + row) * DIM + kt * 32 + c * 8);
            }
        }
        const __nv_bfloat16* bsrc[2] = {Bh, Bl};
        #pragma unroll
        for (int t = 0; t < 2; t++) {
            #pragma unroll
            for (int i = 0; i < 2; i++) {
                int chunk = tid + i * 256;         // 0..511
                int row = chunk >> 2, c = chunk & 3;
                cp_async16(sb + s * STG_B + 2 * A_TILE_B + t * B_TILE_B + row * 80 + c * 16,
                           bsrc[t] + (size_t)(bn + row) * DIM + kt * 32 + c * 8);
            }
        }
        cp_commit();
    };

    load_stage(0, 0);
    load_stage(1, 1);

    const int aRow = lane & 15;
    const int aK16 = (lane >> 4) * 16;
    const int bRow = (lane & 7) + ((lane >> 4) << 3);
    const int bK16 = ((lane >> 3) & 1) * 16;

    for (int kt = 0; kt < 32; kt++) {
        if (kt < 31) asm volatile("cp.async.wait_group 1;" ::: "memory");
        else         asm volatile("cp.async.wait_group 0;" ::: "memory");
        __syncthreads();

        uint32_t st  = sb + (kt & 1) * STG_B;
        uint32_t aHb = st + (warp_m * 64 + aRow) * 80 + aK16;
        uint32_t aLb = aHb + A_TILE_B;
        uint32_t bHb = st + 2 * A_TILE_B + (warp_n * 64 + bRow) * 80 + bK16;
        uint32_t bLb = bHb + B_TILE_B;

        #pragma unroll
        for (int ks = 0; ks < 2; ks++) {
            uint32_t koff = ks * 32;
            uint32_t fah[4][4], fal[4][4], fb[4][4];
            #pragma unroll
            for (int mt = 0; mt < 4; mt++) {
                ldsm4(fah[mt], aHb + mt * 1280 + koff);   // 16 rows * 80
                ldsm4(fal[mt], aLb + mt * 1280 + koff);
            }
            #pragma unroll
            for (int n2 = 0; n2 < 4; n2++)
                ldsm4(fb[n2], bHb + n2 * 1280 + koff);
            // AhBh
            #pragma unroll
            for (int mt = 0; mt < 4; mt++)
                #pragma unroll
                for (int nt = 0; nt < 8; nt++)
                    mma16816(acc[mt][nt], fah[mt],
                             fb[nt >> 1][(nt & 1) * 2], fb[nt >> 1][(nt & 1) * 2 + 1]);
            // AlBh
            #pragma unroll
            for (int mt = 0; mt < 4; mt++)
                #pragma unroll
                for (int nt = 0; nt < 8; nt++)
                    mma16816(acc[mt][nt], fal[mt],
                             fb[nt >> 1][(nt & 1) * 2], fb[nt >> 1][(nt & 1) * 2 + 1]);
            // AhBl (reuse fb registers)
            #pragma unroll
            for (int n2 = 0; n2 < 4; n2++)
                ldsm4(fb[n2], bLb + n2 * 1280 + koff);
            #pragma unroll
            for (int mt = 0; mt < 4; mt++)
                #pragma unroll
                for (int nt = 0; nt < 8; nt++)
                    mma16816(acc[mt][nt], fah[mt],
                             fb[nt >> 1][(nt & 1) * 2], fb[nt >> 1][(nt & 1) * 2 + 1]);
        }
        __syncthreads();
        if (kt + 2 < 32) load_stage(kt + 2, kt & 1);
    }

    const int g = lane >> 2, t2 = (lane & 3) * 2;
    #pragma unroll
    for (int mt = 0; mt < 4; mt++) {
        #pragma unroll
        for (int nt = 0; nt < 8; nt++) {
            int row = bm + warp_m * 64 + mt * 16 + g;
            int col = bn + warp_n * 64 + nt * 8 + t2;
            *(float2*)&C[(size_t)row * DIM + col] =
                make_float2(acc[mt][nt][0], acc[mt][nt][1]);
            *(float2*)&C[(size_t)(row + 8) * DIM + col] =
                make_float2(acc[mt][nt][2], acc[mt][nt][3]);
        }
    }
}

// ===========================================================================
// RoPE + split + relayout: q,k fp32 [row][h*64+d] -> bf16 hi/lo [bh][s][d]
// ===========================================================================
__global__ __launch_bounds__(256) void rope_split_kernel(
    const float* __restrict__ q, const float* __restrict__ k,
    __nv_bfloat16* __restrict__ Qh, __nv_bfloat16* __restrict__ Ql,
    __nv_bfloat16* __restrict__ Kh, __nv_bfloat16* __restrict__ Kl)
{
    int idx = blockIdx.x * 256 + threadIdx.x;   // 2^22 total
    int which = idx >> 21;
    int r   = idx & ((1 << 21) - 1);
    int row = r >> 9;
    int rem = r & 511;
    int head = rem >> 5;
    int i    = rem & 31;

    const float* src = (which ? k : q) + (size_t)row * DIM + head * DH;
    int pos = row & (SEQ - 1);

    float e = (2.0f * (float)i) / (float)DH;
    float theta = exp2f(-e * 19.931568569324174f);   // 1e6^-e
    float ang = (float)pos * theta;
    float sn = sinf(ang), cs = cosf(ang);

    float x1 = src[i], x2 = src[i + 32];
    float y1 = x1 * cs - x2 * sn;
    float y2 = x1 * sn + x2 * cs;

    int b = row >> 11, s = row & (SEQ - 1);
    size_t o = ((size_t)(b * NH + head) * SEQ + s) * DH + i;
    __nv_bfloat16 h1 = __float2bfloat16(y1);
    __nv_bfloat16 h2 = __float2bfloat16(y2);
    __nv_bfloat16* H = which ? Kh : Qh;
    __nv_bfloat16* L = which ? Kl : Ql;
    H[o]      = h1;
    H[o + 32] = h2;
    L[o]      = __float2bfloat16(y1 - __bfloat162float(h1));
    L[o + 32] = __float2bfloat16(y2 - __bfloat162float(h2));
}

// ===========================================================================
// V transpose + split: v fp32 [row][h*64+d] -> bf16 hi/lo [bh][d][s]
// ===========================================================================
__global__ __launch_bounds__(256) void vsplit_kernel(
    const float* __restrict__ v,
    __nv_bfloat16* __restrict__ Vth, __nv_bfloat16* __restrict__ Vtl)
{
    __shared__ float tile[32][33];
    int bh = blockIdx.z;
    int b = bh >> 4, h = bh & 15;
    int s0 = blockIdx.x * 32, d0 = blockIdx.y * 32;
    int tx = threadIdx.x & 31, ty = threadIdx.x >> 5;
    #pragma unroll
    for (int i = 0; i < 32; i += 8)
        tile[ty + i][tx] = v[(size_t)(b * SEQ + s0 + ty + i) * DIM + h * DH + d0 + tx];
    __syncthreads();
    #pragma unroll
    for (int i = 0; i < 32; i += 8) {
        float val = tile[tx][ty + i];   // = v[s0+tx][d0+ty+i]
        __nv_bfloat16 hh = __float2bfloat16(val);
        size_t o = ((size_t)(bh * DH + d0 + ty + i)) * SEQ + s0 + tx;
        Vth[o] = hh;
        Vtl[o] = __float2bfloat16(val - __bfloat162float(hh));
    }
}

// ===========================================================================
// Flash attention via mma.sync, split-bf16 throughout (validated round 4).
// ===========================================================================
#define FP      144                 // smem row pitch (bytes)
#define FQ_OFF  0                   // Qh @0, Ql @18432 (128 rows x 144)
#define FK_OFF  36864               // + stage*18432; Kh +0, Kl +9216 (64x144)
#define FV_OFF  73728               // + stage*18432; Vh +0, Vl +9216 (64x144)
#define FL_SMEM 110592

__global__ __launch_bounds__(256) void flash_mma_kernel(
    const __nv_bfloat16* __restrict__ Qh_, const __nv_bfloat16* __restrict__ Ql_,
    const __nv_bfloat16* __restrict__ Kh_, const __nv_bfloat16* __restrict__ Kl_,
    const __nv_bfloat16* __restrict__ Vth_, const __nv_bfloat16* __restrict__ Vtl_,
    float* __restrict__ ao)
{
    extern __shared__ char smem[];
    uint32_t sb = smem_u32(smem);
    const int tid = threadIdx.x, lane = tid & 31, wid = tid >> 5;
    const int bh = blockIdx.y;
    const int qt = (gridDim.x - 1) - blockIdx.x;   // heavy tiles first
    const int nkt = 2 * (qt + 1);                  // 64-key chunks
    const size_t qkoff = (size_t)bh * SEQ * DH;
    const size_t voff  = (size_t)bh * DH * SEQ;

    // Q tile load (once)
    {
        const __nv_bfloat16* qs[2] = {Qh_ + qkoff, Ql_ + qkoff};
        #pragma unroll
        for (int i = 0; i < 8; i++) {
            int idx = tid + i * 256;           // 0..2047
            int t = idx >> 10, rem = idx & 1023;
            int row = rem >> 3, c = rem & 7;
            cp_async16(sb + FQ_OFF + t * 18432 + row * FP + c * 16,
                       qs[t] + (size_t)(qt * 128 + row) * DH + c * 8);
        }
        cp_commit();
    }

    auto load_kv = [&](int kt, int s) {
        int k0 = kt * 64;
        const __nv_bfloat16* ks_[2] = {Kh_ + qkoff, Kl_ + qkoff};
        const __nv_bfloat16* vs_[2] = {Vth_ + voff, Vtl_ + voff};
        #pragma unroll
        for (int i = 0; i < 4; i++) {
            int idx = tid + i * 256;           // 0..1023
            int t = idx >> 9, rem = idx & 511;
            int row = rem >> 3, c = rem & 7;
            cp_async16(sb + FK_OFF + s * 18432 + t * 9216 + row * FP + c * 16,
                       ks_[t] + (size_t)(k0 + row) * DH + c * 8);
        }
        #pragma unroll
        for (int i = 0; i < 4; i++) {
            int idx = tid + i * 256;
            int t = idx >> 9, rem = idx & 511;
            int row = rem >> 3, c = rem & 7;   // row = dh index, c = key chunk
            cp_async16(sb + FV_OFF + s * 18432 + t * 9216 + row * FP + c * 16,
                       vs_[t] + (size_t)row * SEQ + k0 + c * 8);
        }
        cp_commit();
    };
    load_kv(0, 0);
    load_kv(1, 1);

    const int g = lane >> 2, t2 = (lane & 3) * 2;
    const int aRow = lane & 15, aK16 = (lane >> 4) * 16;
    const int bRow = (lane & 7) + ((lane >> 4) << 3);
    const int bK16 = ((lane >> 3) & 1) * 16;

    asm volatile("cp.async.wait_group 2;" ::: "memory");
    __syncthreads();

    // Q fragments resident: 4 k-steps x (hi, lo)
    uint32_t qh[4][4], ql[4][4];
    {
        uint32_t base = sb + FQ_OFF + (wid * 16 + aRow) * FP + aK16;
        #pragma unroll
        for (int ks = 0; ks < 4; ks++) {
            ldsm4(qh[ks], base + ks * 32);
            ldsm4(ql[ks], base + 18432 + ks * 32);
        }
    }

    float o[8][4];
    #pragma unroll
    for (int nt = 0; nt < 8; nt++)
        #pragma unroll
        for (int j = 0; j < 4; j++) o[nt][j] = 0.f;
    float l0 = 0.f, l1 = 0.f;
    const int row0 = qt * 128 + wid * 16 + g;

    for (int kt = 0; kt < nkt; kt++) {
        if (kt < nkt - 1) asm volatile("cp.async.wait_group 1;" ::: "memory");
        else              asm volatile("cp.async.wait_group 0;" ::: "memory");
        __syncthreads();

        uint32_t stK = sb + FK_OFF + (kt & 1) * 18432;
        uint32_t stV = sb + FV_OFF + (kt & 1) * 18432;

        // ---- S = Q K^T (3-way split) ----
        float S[8][4];
        #pragma unroll
        for (int nt = 0; nt < 8; nt++)
            #pragma unroll
            for (int j = 0; j < 4; j++) S[nt][j] = 0.f;

        #pragma unroll
        for (int ks = 0; ks < 4; ks++) {
            uint32_t fkh[4][4], fkl[4][4];
            #pragma unroll
            for (int n2 = 0; n2 < 4; n2++) {
                uint32_t a = stK + (n2 * 16 + bRow) * FP + bK16 + ks * 32;
                ldsm4(fkh[n2], a);
                ldsm4(fkl[n2], a + 9216);
            }
            #pragma unroll
            for (int nt = 0; nt < 8; nt++) {
                mma16816(S[nt], qh[ks], fkh[nt >> 1][(nt & 1) * 2], fkh[nt >> 1][(nt & 1) * 2 + 1]);
                mma16816(S[nt], qh[ks], fkl[nt >> 1][(nt & 1) * 2], fkl[nt >> 1][(nt & 1) * 2 + 1]);
                mma16816(S[nt], ql[ks], fkh[nt >> 1][(nt & 1) * 2], fkh[nt >> 1][(nt & 1) * 2 + 1]);
            }
        }

        // ---- softmax (no-max) + pack P into A-fragments ----
        uint32_t pah[4][4], pal[4][4];
        int k0 = kt * 64;
        #pragma unroll
        for (int nt = 0; nt < 8; nt++) {
            int col = k0 + nt * 8 + t2;
            float p0 = (col     <= row0)     ? __expf(S[nt][0] * 0.125f) : 0.f;
            float p1 = (col + 1 <= row0)     ? __expf(S[nt][1] * 0.125f) : 0.f;
            float p2 = (col     <= row0 + 8) ? __expf(S[nt][2] * 0.125f) : 0.f;
            float p3 = (col + 1 <= row0 + 8) ? __expf(S[nt][3] * 0.125f) : 0.f;
            l0 += p0 + p1;
            l1 += p2 + p3;
            __nv_bfloat16 h0 = __float2bfloat16(p0), h1 = __float2bfloat16(p1);
            __nv_bfloat16 h2 = __float2bfloat16(p2), h3 = __float2bfloat16(p3);
            float r0 = p0 - __bfloat162float(h0), r1 = p1 - __bfloat162float(h1);
            float r2 = p2 - __bfloat162float(h2), r3 = p3 - __bfloat162float(h3);
            int ks2 = nt >> 1, off = (nt & 1) * 2;
            pah[ks2][off]     = pack2h(h0, h1);
            pah[ks2][off + 1] = pack2h(h2, h3);
            pal[ks2][off]     = pack2f(r0, r1);
            pal[ks2][off + 1] = pack2f(r2, r3);
        }

        // ---- O += P V (3-way split), V^T in smem as [dh][key] ----
        #pragma unroll
        for (int ks2 = 0; ks2 < 4; ks2++) {
            uint32_t fvh[4][4], fvl[4][4];
            #pragma unroll
            for (int n2 = 0; n2 < 4; n2++) {
                uint32_t a = stV + (n2 * 16 + bRow) * FP + bK16 + ks2 * 32;
                ldsm4(fvh[n2], a);
                ldsm4(fvl[n2], a + 9216);
            }
            #pragma unroll
            for (int nt = 0; nt < 8; nt++) {
                mma16816(o[nt], pah[ks2], fvh[nt >> 1][(nt & 1) * 2], fvh[nt >> 1][(nt & 1) * 2 + 1]);
                mma16816(o[nt], pah[ks2], fvl[nt >> 1][(nt & 1) * 2], fvl[nt >> 1][(nt & 1) * 2 + 1]);
                mma16816(o[nt], pal[ks2], fvh[nt >> 1][(nt & 1) * 2], fvh[nt >> 1][(nt & 1) * 2 + 1]);
            }
        }

        __syncthreads();
        if (kt + 2 < nkt) load_kv(kt + 2, kt & 1);
    }

    // row-sum reduce within quads (lanes sharing g)
    l0 += __shfl_xor_sync(0xFFFFFFFFu, l0, 1);
    l0 += __shfl_xor_sync(0xFFFFFFFFu, l0, 2);
    l1 += __shfl_xor_sync(0xFFFFFFFFu, l1, 1);
    l1 += __shfl_xor_sync(0xFFFFFFFFu, l1, 2);
    float inv0 = 1.0f / l0, inv1 = 1.0f / l1;

    int b = bh >> 4, h = bh & 15;
    int srow = qt * 128 + wid * 16 + g;
    #pragma unroll
    for (int nt = 0; nt < 8; nt++) {
        int d = nt * 8 + t2;
        size_t o0 = (size_t)(b * SEQ + srow) * DIM + h * DH + d;
        size_t o1 = (size_t)(b * SEQ + srow + 8) * DIM + h * DH + d;
        *(float2*)&ao[o0] = make_float2(o[nt][0] * inv0, o[nt][1] * inv0);
        *(float2*)&ao[o1] = make_float2(o[nt][2] * inv1, o[nt][3] * inv1);
    }
}

// ===========================================================================
// Launch
// ===========================================================================
extern "C" void kernel_launch(void* const* d_in, const int* in_sizes, int n_in,
                              void* d_out, int out_size)
{
    (void)in_sizes; (void)n_in; (void)out_size;
    const float* x  = (const float*)d_in[0];
    const float* ns = (const float*)d_in[1];
    const float* Wq = (const float*)d_in[2];
    const float* Wk = (const float*)d_in[3];
    const float* Wv = (const float*)d_in[4];
    const float* Wo = (const float*)d_in[5];
    float* out = (float*)d_out;

    float *xn, *qb, *kb, *vb, *ao;
    __nv_bfloat16 *ah, *al, *th, *tl, *qhp, *qlp, *khp, *klp, *vth, *vtl;
    cudaGetSymbolAddress((void**)&xn, g_xn);
    cudaGetSymbolAddress((void**)&qb, g_q);
    cudaGetSymbolAddress((void**)&kb, g_k);
    cudaGetSymbolAddress((void**)&vb, g_v);
    cudaGetSymbolAddress((void**)&ao, g_ao);
    cudaGetSymbolAddress((void**)&ah, g_ah);
    cudaGetSymbolAddress((void**)&al, g_al);
    cudaGetSymbolAddress((void**)&th, g_th);
    cudaGetSymbolAddress((void**)&tl, g_tl);
    cudaGetSymbolAddress((void**)&qhp, g_qh);
    cudaGetSymbolAddress((void**)&qlp, g_ql);
    cudaGetSymbolAddress((void**)&khp, g_kh);
    cudaGetSymbolAddress((void**)&klp, g_kl);
    cudaGetSymbolAddress((void**)&vth, g_vth);
    cudaGetSymbolAddress((void**)&vtl, g_vtl);

    cudaFuncSetAttribute(mma_gemm_kernel,
                         cudaFuncAttributeMaxDynamicSharedMemorySize, GEMM_SMEM);
    cudaFuncSetAttribute(flash_mma_kernel,
                         cudaFuncAttributeMaxDynamicSharedMemorySize, FL_SMEM);

    rmsnorm_kernel<<<ROWS, 256>>>(x, ns, xn);
    asplit_kernel<<<(ROWS * DIM) / (256 * 4), 256>>>(xn, ah, al);

    dim3 gg(DIM / 128, ROWS / 256);   // (8, 16) = 128 blocks
    dim3 wg(DIM / 32, DIM / 32);      // (32, 32)

    wsplit_kernel<<<wg, 256>>>(Wq, th, tl);
    mma_gemm_kernel<<<gg, 256, GEMM_SMEM>>>(ah, al, th, tl, qb);
    wsplit_kernel<<<wg, 256>>>(Wk, th, tl);
    mma_gemm_kernel<<<gg, 256, GEMM_SMEM>>>(ah, al, th, tl, kb);
    wsplit_kernel<<<wg, 256>>>(Wv, th, tl);
    mma_gemm_kernel<<<gg, 256, GEMM_SMEM>>>(ah, al, th, tl, vb);

    rope_split_kernel<<<(2 * ROWS * NH * 32) / 256, 256>>>(qb, kb, qhp, qlp, khp, klp);
    vsplit_kernel<<<dim3(SEQ / 32, DH / 32, BATCH * NH), 256>>>(vb, vth, vtl);

    flash_mma_kernel<<<dim3(SEQ / 128, BATCH * NH), 256, FL_SMEM>>>(
        qhp, qlp, khp, klp, vth, vtl, ao);

    asplit_kernel<<<(ROWS * DIM) / (256 * 4), 256>>>(ao, ah, al);
    wsplit_kernel<<<wg, 256>>>(Wo, th, tl);
    mma_gemm_kernel<<<gg, 256, GEMM_SMEM>>>(ah, al, th, tl, out);
}